// round 1
// baseline (speedup 1.0000x reference)
#include <cuda_runtime.h>
#include <cstdint>

#define N_IMG 16
#define CIN   32
#define COUT  32
#define HH    256
#define WW    256
#define HW    (HH * WW)
#define EPSV  1e-5f

// ---- scratch (no allocations allowed -> __device__ globals) ----
__device__ uint32_t g_xpack[N_IMG * HW];     // 4 MiB packed sign bits, bit c = sign(x[c]) >= 0
__device__ uint32_t g_wpack[COUT * 12];      // padded stride 12 for LDS.128
__device__ int      g_wcorr[COUT * 12];      // 32 - 2*popc(w) per tap (border correction)
__device__ float    g_scale[COUT];
__device__ float    g_bias[COUT];

// ============================================================================
// Pack x: NCHW float32 -> per-pixel 32-bit sign word (bit c = channel c sign).
// Warp handles 32 consecutive pixels; loops channels with coalesced 128B lines
// and uses ballot to transpose pixel-major sign bits into channel-major words.
// ============================================================================
__global__ __launch_bounds__(256) void pack_x_kernel(const float* __restrict__ x) {
    int warp = (blockIdx.x * blockDim.x + threadIdx.x) >> 5;
    int lane = threadIdx.x & 31;
    int p0   = warp << 5;                 // first of 32 pixels (within flat n*HW)
    int n    = p0 >> 16;                  // HW = 65536
    int s    = p0 & (HW - 1);
    const float* xp = x + (size_t)n * CIN * HW + s + lane;
    uint32_t word = 0;
#pragma unroll
    for (int c = 0; c < CIN; ++c) {
        float v = xp[c * HW];
        unsigned m = __ballot_sync(0xFFFFFFFFu, v >= 0.0f);
        word |= ((m >> lane) & 1u) << c;
    }
    g_xpack[p0 + lane] = word;
}

// ============================================================================
// Pack weights (tiny) + fold BN into scale/bias.
// wb = sign(sign(w)+0.01): w>=0 -> +1, w<0 -> -1  => bit = (w >= 0)
// ============================================================================
__global__ void pack_w_kernel(const float* __restrict__ wgt,
                              const float* __restrict__ gamma,
                              const float* __restrict__ beta,
                              const float* __restrict__ mean,
                              const float* __restrict__ var) {
    int t = threadIdx.x;
    if (t < COUT * 9) {
        int co = t / 9, tap = t % 9;
        uint32_t word = 0;
        for (int ci = 0; ci < CIN; ++ci) {
            float v = wgt[(co * CIN + ci) * 9 + tap];
            word |= (v >= 0.0f ? 1u : 0u) << ci;
        }
        g_wpack[co * 12 + tap] = word;
        g_wcorr[co * 12 + tap] = 32 - 2 * __popc(word);
    } else if (t < COUT * 9 + COUT) {
        int c = t - COUT * 9;
        float inv = gamma[c] * rsqrtf(var[c] + EPSV);
        g_scale[c] = inv;
        g_bias[c]  = beta[c] - mean[c] * inv;
    }
}

// ============================================================================
// Conv: each block = (n, 8 rows x 128 cols) output tile, all 32 couts.
// Thread = 4 consecutive output pixels (STG.128), loops couts.
// Input tile (10 x 130 words, zero-filled halo) staged in smem.
// val = 288 - 2*sum_popc; border taps corrected by precomputed (32-2*popc(w)).
// ============================================================================
__global__ __launch_bounds__(256) void conv_kernel(float* __restrict__ out) {
    __shared__ uint32_t tile[10][132];       // stride 132 -> 16B-aligned rows
    __shared__ uint32_t wsm[COUT * 12];
    __shared__ int      csm[COUT * 12];
    __shared__ float    ssm[COUT], bsm[COUT];

    int tid     = threadIdx.x;
    int n       = blockIdx.z;
    int rowbase = blockIdx.y * 8;
    int colbase = blockIdx.x * 128;

    for (int i = tid; i < COUT * 12; i += 256) { wsm[i] = g_wpack[i]; csm[i] = g_wcorr[i]; }
    if (tid < COUT) { ssm[tid] = g_scale[tid]; bsm[tid] = g_bias[tid]; }

    const uint32_t* xp = g_xpack + n * HW;
    for (int i = tid; i < 10 * 130; i += 256) {
        int r = i / 130, c = i % 130;
        int h = rowbase - 1 + r;
        int w = colbase - 1 + c;
        uint32_t v = 0;
        if ((unsigned)h < HH && (unsigned)w < WW) v = xp[h * WW + w];
        tile[r][c] = v;
    }
    __syncthreads();

    int ty = tid >> 5, tx = tid & 31;
    int h  = rowbase + ty;
    int w0 = colbase + tx * 4;

    // 3 rows x 6 cols of input words cover the 4-pixel window
    uint32_t a[3][6];
#pragma unroll
    for (int r = 0; r < 3; ++r) {
        const uint32_t* rp = &tile[ty + r][tx * 4];
        uint4 v4 = *reinterpret_cast<const uint4*>(rp);
        uint2 v2 = *reinterpret_cast<const uint2*>(rp + 4);
        a[r][0] = v4.x; a[r][1] = v4.y; a[r][2] = v4.z;
        a[r][3] = v4.w; a[r][4] = v2.x; a[r][5] = v2.y;
    }

    bool btop = (h == 0), bbot = (h == HH - 1);
    bool anyb = btop | bbot | (w0 == 0) | (w0 + 3 == WW - 1);

    float* op = out + (size_t)n * COUT * HW + h * WW + w0;

#pragma unroll 4
    for (int co = 0; co < COUT; ++co) {
        const uint32_t* wp = &wsm[co * 12];
        uint4 wa  = *reinterpret_cast<const uint4*>(wp);
        uint4 wbv = *reinterpret_cast<const uint4*>(wp + 4);
        uint32_t wv0 = wa.x,  wv1 = wa.y,  wv2 = wa.z;
        uint32_t wv3 = wa.w,  wv4 = wbv.x, wv5 = wbv.y;
        uint32_t wv6 = wbv.z, wv7 = wbv.w, wv8 = wp[8];
        float s = ssm[co], b = bsm[co];
        float4 res;
        float* rp = &res.x;
#pragma unroll
        for (int p = 0; p < 4; ++p) {
            int d = __popc(a[0][p] ^ wv0) + __popc(a[0][p + 1] ^ wv1) + __popc(a[0][p + 2] ^ wv2)
                  + __popc(a[1][p] ^ wv3) + __popc(a[1][p + 1] ^ wv4) + __popc(a[1][p + 2] ^ wv5)
                  + __popc(a[2][p] ^ wv6) + __popc(a[2][p + 1] ^ wv7) + __popc(a[2][p + 2] ^ wv8);
            int val = 288 - 2 * d;
            if (anyb) {
                const int* c9 = &csm[co * 12];
                int w = w0 + p;
                int corr = 0;
                if (btop) corr += c9[0] + c9[1] + c9[2];
                if (bbot) corr += c9[6] + c9[7] + c9[8];
                if (w == 0) {
                    corr += c9[0] + c9[3] + c9[6];
                    if (btop) corr -= c9[0];
                    if (bbot) corr -= c9[6];
                }
                if (w == WW - 1) {
                    corr += c9[2] + c9[5] + c9[8];
                    if (btop) corr -= c9[2];
                    if (bbot) corr -= c9[8];
                }
                val -= corr;
            }
            rp[p] = fmaxf(fmaf(s, (float)val, b), 0.0f);
        }
        *reinterpret_cast<float4*>(op + co * HW) = res;
    }
}

extern "C" void kernel_launch(void* const* d_in, const int* in_sizes, int n_in,
                              void* d_out, int out_size) {
    const float* x     = (const float*)d_in[0];
    const float* wgt   = (const float*)d_in[1];
    const float* gamma = (const float*)d_in[2];
    const float* beta  = (const float*)d_in[3];
    const float* mean  = (const float*)d_in[4];
    const float* var   = (const float*)d_in[5];
    float* out = (float*)d_out;

    pack_x_kernel<<<4096, 256>>>(x);           // 1,048,576 threads = 1 word/pixel
    pack_w_kernel<<<1, 320>>>(wgt, gamma, beta, mean, var);
    dim3 grid(2, 32, 16);                       // (W/128, H/8, N)
    conv_kernel<<<grid, 256>>>(out);
}

// round 2
// speedup vs baseline: 1.0958x; 1.0958x over previous
#include <cuda_runtime.h>
#include <cstdint>

#define N_IMG 16
#define CIN   32
#define COUT  32
#define HH    256
#define WW    256
#define HW    (HH * WW)
#define EPSV  1e-5f

// ---- scratch (no allocations allowed -> __device__ globals) ----
__device__ uint32_t g_xpack[N_IMG * HW];     // 4 MiB packed sign bits, bit c = (x[c] >= 0)
__device__ uint32_t g_wpack[COUT * 12];      // stride 12 -> 48B, 16B-aligned rows
__device__ float    g_scale[COUT];
__device__ float    g_bias[COUT];

// ============================================================================
// Pack x: NCHW float32 -> per-pixel 32-bit sign word. Thread = 4 consecutive
// pixels; float4 loads per channel (coalesced 128B/warp lines), local bit
// builds (no ballot), uint4 store.
// ============================================================================
__global__ __launch_bounds__(256) void pack_x_kernel(const float* __restrict__ x) {
    int g  = blockIdx.x * 256 + threadIdx.x;
    int p0 = g << 2;                       // first of 4 pixels (flat n*HW)
    int n  = p0 >> 16;                     // HW = 65536
    int s  = p0 & (HW - 1);
    const float4* xp = reinterpret_cast<const float4*>(x + (size_t)n * CIN * HW + s);
    uint32_t w0 = 0, w1 = 0, w2 = 0, w3 = 0;
#pragma unroll
    for (int c = 0; c < CIN; ++c) {
        float4 v = xp[c * (HW / 4)];
        uint32_t b = 1u << c;
        if (v.x >= 0.0f) w0 |= b;
        if (v.y >= 0.0f) w1 |= b;
        if (v.z >= 0.0f) w2 |= b;
        if (v.w >= 0.0f) w3 |= b;
    }
    *reinterpret_cast<uint4*>(&g_xpack[p0]) = make_uint4(w0, w1, w2, w3);
}

// ============================================================================
// Pack weights + fold BN. wb = sign(sign(w)+0.01): bit = (w >= 0).
// ============================================================================
__global__ void pack_w_kernel(const float* __restrict__ wgt,
                              const float* __restrict__ gamma,
                              const float* __restrict__ beta,
                              const float* __restrict__ mean,
                              const float* __restrict__ var) {
    int t = threadIdx.x;
    if (t < COUT * 12) {
        int co = t / 12, tap = t % 12;
        uint32_t word = 0;
        if (tap < 9) {
            for (int ci = 0; ci < CIN; ++ci) {
                float v = wgt[(co * CIN + ci) * 9 + tap];
                word |= (v >= 0.0f ? 1u : 0u) << ci;
            }
        }
        g_wpack[t] = word;
    }
    if (t < COUT) {
        float inv = gamma[t] * rsqrtf(var[t] + EPSV);
        g_scale[t] = inv;
        g_bias[t]  = beta[t] - mean[t] * inv;
    }
}

// ============================================================================
// Conv: block = (n, cout-group of 8, 16 rows x 128 cols). Warp owns ONE cout:
// 9 weight words + BN consts + border scalars in registers; inner loop is
// pure LDS(tile) + XOR + POPC + IADD tree + FFMA/FMAX + STG.128.
// val = 288 - 2*(d + adj); adj_t = 16 - popc(w_t) summed over padded taps.
// ============================================================================
__global__ __launch_bounds__(256) void conv_kernel(float* __restrict__ out) {
    __shared__ uint32_t tile[18][132];       // 16+2 halo rows, 130 used cols

    int tid     = threadIdx.x;
    int n       = blockIdx.z >> 2;
    int cg      = blockIdx.z & 3;
    int rowbase = blockIdx.y * 16;
    int colbase = blockIdx.x * 128;

    const uint32_t* xp = g_xpack + n * HW;
    for (int i = tid; i < 18 * 130; i += 256) {
        int r = i / 130, c = i % 130;
        int h = rowbase - 1 + r;
        int w = colbase - 1 + c;
        uint32_t v = 0;
        if ((unsigned)h < HH && (unsigned)w < WW) v = xp[h * WW + w];
        tile[r][c] = v;
    }

    int wid = tid >> 5, tx = tid & 31;
    int co  = cg * 8 + wid;

    // weights for this warp's cout -> registers (broadcast LDG, L2-hot)
    const uint4* wp4 = reinterpret_cast<const uint4*>(&g_wpack[co * 12]);
    uint4 wa = wp4[0], wb = wp4[1], wc = wp4[2];
    uint32_t wv0 = wa.x, wv1 = wa.y, wv2 = wa.z, wv3 = wa.w;
    uint32_t wv4 = wb.x, wv5 = wb.y, wv6 = wb.z, wv7 = wb.w;
    uint32_t wv8 = wc.x;

    float sc = g_scale[co], bi = g_bias[co];
    float s2 = -2.0f * sc;
    float b2 = fmaf(288.0f, sc, bi);

    int pw0 = 16 - __popc(wv0), pw1 = 16 - __popc(wv1), pw2 = 16 - __popc(wv2);
    int pw3 = 16 - __popc(wv3),                          pw5 = 16 - __popc(wv5);
    int pw6 = 16 - __popc(wv6), pw7 = 16 - __popc(wv7), pw8 = 16 - __popc(wv8);
    int adjT = pw0 + pw1 + pw2;
    int adjB = pw6 + pw7 + pw8;
    int adjL = pw0 + pw3 + pw6;
    int adjR = pw2 + pw5 + pw8;

    int  w0c = colbase + tx * 4;
    bool isL = (w0c == 0);
    bool isR = (w0c + 3 == WW - 1);
    int baseL = isL ? adjL : 0;
    int baseR = isR ? adjR : 0;
    int dt0 = adjT - (isL ? pw0 : 0), dt3 = adjT - (isR ? pw2 : 0);
    int db0 = adjB - (isL ? pw6 : 0), db3 = adjB - (isR ? pw8 : 0);

    __syncthreads();

    float* op = out + ((size_t)(n * COUT + co)) * HW + rowbase * WW + w0c;

#pragma unroll 4
    for (int r = 0; r < 16; ++r) {
        const uint32_t* r0 = &tile[r][tx * 4];
        const uint32_t* r1 = &tile[r + 1][tx * 4];
        const uint32_t* r2 = &tile[r + 2][tx * 4];
        uint4 A0 = *reinterpret_cast<const uint4*>(r0);
        uint2 B0 = *reinterpret_cast<const uint2*>(r0 + 4);
        uint4 A1 = *reinterpret_cast<const uint4*>(r1);
        uint2 B1 = *reinterpret_cast<const uint2*>(r1 + 4);
        uint4 A2 = *reinterpret_cast<const uint4*>(r2);
        uint2 B2 = *reinterpret_cast<const uint2*>(r2 + 4);
        uint32_t a0[6] = {A0.x, A0.y, A0.z, A0.w, B0.x, B0.y};
        uint32_t a1[6] = {A1.x, A1.y, A1.z, A1.w, B1.x, B1.y};
        uint32_t a2[6] = {A2.x, A2.y, A2.z, A2.w, B2.x, B2.y};

        int d[4];
#pragma unroll
        for (int p = 0; p < 4; ++p) {
            d[p] = __popc(a0[p] ^ wv0) + __popc(a0[p + 1] ^ wv1) + __popc(a0[p + 2] ^ wv2)
                 + __popc(a1[p] ^ wv3) + __popc(a1[p + 1] ^ wv4) + __popc(a1[p + 2] ^ wv5)
                 + __popc(a2[p] ^ wv6) + __popc(a2[p + 1] ^ wv7) + __popc(a2[p + 2] ^ wv8);
        }
        d[0] += baseL;
        d[3] += baseR;
        int h = rowbase + r;
        if (h == 0)      { d[0] += dt0; d[1] += adjT; d[2] += adjT; d[3] += dt3; }
        if (h == HH - 1) { d[0] += db0; d[1] += adjB; d[2] += adjB; d[3] += db3; }

        float4 res;
        res.x = fmaxf(fmaf(s2, (float)d[0], b2), 0.0f);
        res.y = fmaxf(fmaf(s2, (float)d[1], b2), 0.0f);
        res.z = fmaxf(fmaf(s2, (float)d[2], b2), 0.0f);
        res.w = fmaxf(fmaf(s2, (float)d[3], b2), 0.0f);
        *reinterpret_cast<float4*>(op + r * WW) = res;
    }
}

extern "C" void kernel_launch(void* const* d_in, const int* in_sizes, int n_in,
                              void* d_out, int out_size) {
    const float* x     = (const float*)d_in[0];
    const float* wgt   = (const float*)d_in[1];
    const float* gamma = (const float*)d_in[2];
    const float* beta  = (const float*)d_in[3];
    const float* mean  = (const float*)d_in[4];
    const float* var   = (const float*)d_in[5];
    float* out = (float*)d_out;

    pack_x_kernel<<<1024, 256>>>(x);                 // 4 pixels/thread
    pack_w_kernel<<<1, 384>>>(wgt, gamma, beta, mean, var);
    dim3 grid(2, 16, 64);                            // (W/128, H/16, N * 4 cout-groups)
    conv_kernel<<<grid, 256>>>(out);
}

// round 4
// speedup vs baseline: 1.1823x; 1.0790x over previous
#include <cuda_runtime.h>
#include <cstdint>

#define N_IMG 16
#define CIN   32
#define COUT  32
#define HH    256
#define WW    256
#define HW    (HH * WW)
#define EPSV  1e-5f

// ---- scratch (no allocations allowed -> __device__ globals) ----
__device__ uint32_t g_xpack[N_IMG * HW];   // packed sign bits, bit c = (x[c] >= 0)

// ============================================================================
// Pack x: NCHW f32 -> per-pixel 32-bit sign word. Thread = 4 pixels.
// Channels staged in batches of 8 float4 -> MLP ~8 for DRAM saturation.
// ============================================================================
__global__ __launch_bounds__(256) void pack_x_kernel(const float* __restrict__ x) {
    int g  = blockIdx.x * 256 + threadIdx.x;
    int p0 = g << 2;
    int n  = p0 >> 16;                     // HW = 65536
    int s  = p0 & (HW - 1);
    const float4* xp = reinterpret_cast<const float4*>(x + (size_t)n * CIN * HW + s);
    uint32_t w0 = 0, w1 = 0, w2 = 0, w3 = 0;
#pragma unroll
    for (int c0 = 0; c0 < CIN; c0 += 8) {
        float4 v[8];
#pragma unroll
        for (int j = 0; j < 8; ++j) v[j] = xp[(c0 + j) * (HW / 4)];
#pragma unroll
        for (int j = 0; j < 8; ++j) {
            uint32_t b = 1u << (c0 + j);
            if (v[j].x >= 0.0f) w0 |= b;
            if (v[j].y >= 0.0f) w1 |= b;
            if (v[j].z >= 0.0f) w2 |= b;
            if (v[j].w >= 0.0f) w3 |= b;
        }
    }
    *reinterpret_cast<uint4*>(&g_xpack[p0]) = make_uint4(w0, w1, w2, w3);
}

__device__ __forceinline__ void csa(uint32_t a, uint32_t b, uint32_t c,
                                    uint32_t& s, uint32_t& cy) {
    s  = a ^ b ^ c;                     // LOP3 0x96
    cy = (a & b) | (c & (a | b));       // LOP3 0xE8 (majority)
}

// ============================================================================
// Conv: block = (n, cout-group of 8, 16 rows x 128 cols). Warp owns one cout.
// Weights packed in-prologue via ballot (no pack_w kernel). Inner loop:
// 9 XOR + 5 CSA (10 LOP3) + 4 POPC per pixel (POPC is quarter-rate ->
// CSA compression is the win), exact int->float bit hack (no I2F).
// val = 288 - 2*(d + adj); u = 800 - 2*dd; out = sc*(u-512) + bias.
// ============================================================================
__global__ __launch_bounds__(256) void conv_kernel(
        float* __restrict__ out,
        const float* __restrict__ wgt,
        const float* __restrict__ gamma, const float* __restrict__ beta,
        const float* __restrict__ mean,  const float* __restrict__ var) {
    __shared__ uint32_t tile[18][132];       // 16+2 halo rows, 130 used cols

    int tid     = threadIdx.x;
    int n       = blockIdx.z >> 2;
    int cg      = blockIdx.z & 3;
    int rowbase = blockIdx.y * 16;
    int colbase = blockIdx.x * 128;

    const uint32_t* xp = g_xpack + n * HW;
    for (int i = tid; i < 18 * 130; i += 256) {
        int r = i / 130, c = i % 130;
        int h = rowbase - 1 + r;
        int w = colbase - 1 + c;
        uint32_t v = 0;
        if ((unsigned)h < HH && (unsigned)w < WW) v = xp[h * WW + w];
        tile[r][c] = v;
    }

    int wid = tid >> 5, tx = tid & 31;
    int co  = cg * 8 + wid;

    // pack this warp's cout weights via ballot: lane = input channel
    // wb = sign(sign(w)+0.01) -> bit = (w >= 0)
    const float* wp = wgt + (size_t)co * CIN * 9 + tx * 9;
    uint32_t wv0 = __ballot_sync(0xFFFFFFFFu, wp[0] >= 0.0f);
    uint32_t wv1 = __ballot_sync(0xFFFFFFFFu, wp[1] >= 0.0f);
    uint32_t wv2 = __ballot_sync(0xFFFFFFFFu, wp[2] >= 0.0f);
    uint32_t wv3 = __ballot_sync(0xFFFFFFFFu, wp[3] >= 0.0f);
    uint32_t wv4 = __ballot_sync(0xFFFFFFFFu, wp[4] >= 0.0f);
    uint32_t wv5 = __ballot_sync(0xFFFFFFFFu, wp[5] >= 0.0f);
    uint32_t wv6 = __ballot_sync(0xFFFFFFFFu, wp[6] >= 0.0f);
    uint32_t wv7 = __ballot_sync(0xFFFFFFFFu, wp[7] >= 0.0f);
    uint32_t wv8 = __ballot_sync(0xFFFFFFFFu, wp[8] >= 0.0f);

    float sc = gamma[co] * rsqrtf(var[co] + EPSV);
    float bb = (beta[co] - mean[co] * sc) - 512.0f * sc;   // out = fma(sc, u, bb)

    int pw0 = 16 - __popc(wv0), pw1 = 16 - __popc(wv1), pw2 = 16 - __popc(wv2);
    int pw3 = 16 - __popc(wv3),                          pw5 = 16 - __popc(wv5);
    int pw6 = 16 - __popc(wv6), pw7 = 16 - __popc(wv7), pw8 = 16 - __popc(wv8);
    int adjT = pw0 + pw1 + pw2;
    int adjB = pw6 + pw7 + pw8;
    int adjL = pw0 + pw3 + pw6;
    int adjR = pw2 + pw5 + pw8;

    int  w0c = colbase + tx * 4;
    bool isL = (w0c == 0);
    bool isR = (w0c + 3 == WW - 1);
    int baseL = isL ? adjL : 0;
    int baseR = isR ? adjR : 0;
    int dt0 = adjT - (isL ? pw0 : 0), dt3 = adjT - (isR ? pw2 : 0);
    int db0 = adjB - (isL ? pw6 : 0), db3 = adjB - (isR ? pw8 : 0);

    __syncthreads();

    float* op = out + ((size_t)(n * COUT + co)) * HW + rowbase * WW + w0c;

#pragma unroll 2
    for (int r = 0; r < 16; ++r) {
        const uint32_t* r0 = &tile[r][tx * 4];
        const uint32_t* r1 = &tile[r + 1][tx * 4];
        const uint32_t* r2 = &tile[r + 2][tx * 4];
        uint4 A0 = *reinterpret_cast<const uint4*>(r0);
        uint2 B0 = *reinterpret_cast<const uint2*>(r0 + 4);
        uint4 A1 = *reinterpret_cast<const uint4*>(r1);
        uint2 B1 = *reinterpret_cast<const uint2*>(r1 + 4);
        uint4 A2 = *reinterpret_cast<const uint4*>(r2);
        uint2 B2 = *reinterpret_cast<const uint2*>(r2 + 4);
        uint32_t a0[6] = {A0.x, A0.y, A0.z, A0.w, B0.x, B0.y};
        uint32_t a1[6] = {A1.x, A1.y, A1.z, A1.w, B1.x, B1.y};
        uint32_t a2[6] = {A2.x, A2.y, A2.z, A2.w, B2.x, B2.y};

        int d[4];
#pragma unroll
        for (int p = 0; p < 4; ++p) {
            uint32_t s1, c1, s2, c2, s3, c3, s4, c4, s5, c5;
            csa(a0[p] ^ wv0, a0[p + 1] ^ wv1, a0[p + 2] ^ wv2, s1, c1);
            csa(a1[p] ^ wv3, a1[p + 1] ^ wv4, a1[p + 2] ^ wv5, s2, c2);
            csa(a2[p] ^ wv6, a2[p + 1] ^ wv7, a2[p + 2] ^ wv8, s3, c3);
            csa(s1, s2, s3, s4, c4);
            csa(c1, c2, c3, s5, c5);
            int t = __popc(c4) + __popc(s5);
            d[p] = __popc(s4) + 2 * t + 4 * __popc(c5);
        }
        d[0] += baseL;
        d[3] += baseR;
        int h = rowbase + r;
        if (h == 0)      { d[0] += dt0; d[1] += adjT; d[2] += adjT; d[3] += dt3; }
        if (h == HH - 1) { d[0] += db0; d[1] += adjB; d[2] += adjB; d[3] += db3; }

        float4 res;
        float* rp = &res.x;
#pragma unroll
        for (int p = 0; p < 4; ++p) {
            int u = 800 - 2 * d[p];                       // in [32, 992] -> exact
            float fu = __int_as_float(0x4B000000u | (uint32_t)u) - 8388608.0f;
            rp[p] = fmaxf(fmaf(sc, fu, bb), 0.0f);
        }
        *reinterpret_cast<float4*>(op + r * WW) = res;
    }
}

extern "C" void kernel_launch(void* const* d_in, const int* in_sizes, int n_in,
                              void* d_out, int out_size) {
    const float* x     = (const float*)d_in[0];
    const float* wgt   = (const float*)d_in[1];
    const float* gamma = (const float*)d_in[2];
    const float* beta  = (const float*)d_in[3];
    const float* mean  = (const float*)d_in[4];
    const float* var   = (const float*)d_in[5];
    float* out = (float*)d_out;

    pack_x_kernel<<<1024, 256>>>(x);                 // 4 pixels/thread
    dim3 grid(2, 16, 64);                            // (W/128, H/16, N * 4 cout-groups)
    conv_kernel<<<grid, 256>>>(out, wgt, gamma, beta, mean, var);
}